// round 15
// baseline (speedup 1.0000x reference)
#include <cuda_runtime.h>
#include <math.h>
#include <stdint.h>

// ---------------------------------------------------------------------------
// Shapes
// ---------------------------------------------------------------------------
#define BATCH  8192
#define DIN    4096
#define DMODEL 512
#define FDIM   2048
#define NH     3
#define HD     256
#define OUTD   896

// big GEMM tile (128x256, 8 warps of 64x64), BK=32, 3-stage  (R12 proven)
#define BM 128
#define BN 256
#define BK 32
#define THREADS 256
#define AST 36
#define A_STAGE (BM * AST)
#define B_STAGE (4 * BN * 8)
#define STAGE (A_STAGE + B_STAGE)
#define SMB_BIG (3 * STAGE * 4)            // 153600 B

// small GEMM tile (128x128, 8 warps of 32x64), BK=32, 2-stage, 2 CTA/SM
#define SBN 128
#define SSTAGE (A_STAGE + 4 * SBN * 8)
#define SMB_SM (2 * SSTAGE * 4)            // 69632 B

// Epilogue flags
#define F_B2   1
#define F_GELU 2
#define F_RES  4
#define F_LNA  8
#define F_STAT 16

// ---------------------------------------------------------------------------
// Scratch
// ---------------------------------------------------------------------------
__device__ float g_h  [BATCH * DMODEL];
__device__ float g_cat[BATCH * 2 * DMODEL];
__device__ float g_ff [BATCH * FDIM];
__device__ float g_z  [BATCH * NH * HD];

__device__ float g_wp_in [DIN * DMODEL];
__device__ float g_wp_o  [2 * DMODEL * DMODEL];
__device__ float g_wp_stk[2 * DMODEL * DMODEL];
__device__ float g_wp_ff1[DMODEL * FDIM];
__device__ float g_wp_ff2[FDIM * DMODEL];
__device__ float g_wp_h1 [NH * DMODEL * HD];
__device__ float g_wp_h2 [NH * HD * OUTD];

__device__ float g_bstk[DMODEL];

__device__ float g_v1_ff1[FDIM];
__device__ float g_v2_ff1[FDIM];
__device__ float g_v1_h1 [NH * HD];
__device__ float g_v2_h1 [NH * HD];
__device__ float g_v1_h2 [NH * OUTD];
__device__ float g_v2_h2 [NH * OUTD];

// raw row stats {sum, sumsq}
__device__ float2 g_rs_ln3 [BATCH];
__device__ float2 g_rs_lout[BATCH];
__device__ float2 g_rs_lnh [BATCH * NH];

// ---------------------------------------------------------------------------
// Helpers
// ---------------------------------------------------------------------------
static __device__ __forceinline__ void cp16(float* sm, const float* gm) {
    unsigned s = (unsigned)__cvta_generic_to_shared(sm);
    asm volatile("cp.async.ca.shared.global [%0], [%1], 16;\n" :: "r"(s), "l"(gm));
}
static __device__ __forceinline__ unsigned f2tf32(float f) {
    unsigned u;
    asm("cvt.rna.tf32.f32 %0, %1;" : "=r"(u) : "f"(f));
    return u;
}
static __device__ __forceinline__ float gelu_exact(float v) {
    return 0.5f * v * (1.0f + erff(v * 0.70710678118654752f));
}
#define MMA_TF32(acc, a0, a1, a2, a3, b0, b1)                                  \
    asm volatile(                                                              \
        "mma.sync.aligned.m16n8k8.row.col.f32.tf32.tf32.f32 "                  \
        "{%0,%1,%2,%3},{%4,%5,%6,%7},{%8,%9},{%0,%1,%2,%3};\n"                 \
        : "+f"((acc)[0]), "+f"((acc)[1]), "+f"((acc)[2]), "+f"((acc)[3])       \
        : "r"(a0), "r"(a1), "r"(a2), "r"(a3), "r"(b0), "r"(b1))

// ---------------------------------------------------------------------------
// BIG GEMM (R12-proven)
// ---------------------------------------------------------------------------
template<int FLAGS>
__global__ void __launch_bounds__(THREADS, 1) gemm_big(
    const float* __restrict__ A, int lda, long sA,
    const float* __restrict__ B, int ldbN, long sB,
    float* __restrict__ C, int ldc, long sC,
    int K,
    const float* __restrict__ bias, int sBias,
    const float* __restrict__ bias2,
    const float* __restrict__ res,
    const float2* __restrict__ rs, int rsStride, float invC,
    const float* __restrict__ v1, const float* __restrict__ v2, long vZ,
    float2* __restrict__ stat, int statStride, int statZ)
{
    extern __shared__ float sm[];
    const int tid  = threadIdx.x;
    const int lane = tid & 31;
    const int warp = tid >> 5;
    const int wm = warp & 1;
    const int wn = warp >> 1;
    const int q  = lane >> 2, cc = lane & 3;

    const int z = blockIdx.z;
    A    += (long)z * sA;
    B    += (long)z * sB;
    C    += (long)z * sC;
    bias += (long)z * sBias;
    const float* resb = (FLAGS & F_RES) ? (res + (long)z * sC) : nullptr;
    if (FLAGS & F_LNA) { v1 += (long)z * vZ; v2 += (long)z * vZ; }
    if (FLAGS & F_STAT) stat += (long)z * statZ;

    const long mBase = (long)blockIdx.y * BM;
    const int  nBase = blockIdx.x * BN;
    const float* Ag = A + mBase * lda;

    const int numK = K / BK;

    float4 fA[4];
    auto ldgA = [&](int kt) {
#pragma unroll
        for (int i = 0; i < 4; i++) {
            int f = i * THREADS + tid;
            int r = f >> 3, c = (f & 7) * 4;
            fA[i] = *(const float4*)(Ag + (long)r * lda + kt * BK + c);
        }
    };
    auto stsA = [&](int stg) {
        float* As = sm + stg * STAGE;
#pragma unroll
        for (int i = 0; i < 4; i++) {
            int f = i * THREADS + tid;
            int r = f >> 3, c = (f & 7) * 4;
            float4 v = fA[i];
            *(uint4*)(As + r * AST + c) =
                make_uint4(f2tf32(v.x), f2tf32(v.y), f2tf32(v.z), f2tf32(v.w));
        }
    };
    auto cpB = [&](int kt, int stg) {
        float* Bs = sm + stg * STAGE + A_STAGE;
#pragma unroll
        for (int i = 0; i < 8; i++) {
            int idx = i * THREADS + tid;
            int half = idx & 1;
            int n = (idx >> 1) & 255;
            int g = idx >> 9;
            const float* src = B + ((long)(kt * 4 + g) * ldbN + nBase + n) * 8 + half * 4;
            cp16(Bs + (g * BN + n) * 8 + half * 4, src);
        }
    };

    float acc[4][8][4];
#pragma unroll
    for (int a = 0; a < 4; a++)
#pragma unroll
        for (int b = 0; b < 8; b++)
#pragma unroll
            for (int c = 0; c < 4; c++) acc[a][b][c] = 0.f;

    ldgA(0); stsA(0);
    cpB(0, 0);
    asm volatile("cp.async.commit_group;\n" ::: "memory");
    ldgA(1);
    cpB(1, 1);
    asm volatile("cp.async.commit_group;\n" ::: "memory");

    for (int kt = 0; kt < numK; kt++) {
        asm volatile("cp.async.wait_group 1;\n" ::: "memory");
        __syncthreads();

        if (kt + 1 < numK) stsA((kt + 1) % 3);
        if (kt + 2 < numK) { ldgA(kt + 2); cpB(kt + 2, (kt + 2) % 3); }
        asm volatile("cp.async.commit_group;\n" ::: "memory");

        const float* As = sm + (kt % 3) * STAGE + (wm * 64) * AST;
        const float* Bs = sm + (kt % 3) * STAGE + A_STAGE;

#pragma unroll
        for (int ks = 0; ks < 4; ks++) {
            uint32_t af[4][4];
#pragma unroll
            for (int mi = 0; mi < 4; mi++) {
                const float* ap = As + (mi * 16 + q) * AST + ks * 8 + cc;
                af[mi][0] = __float_as_uint(ap[0]);
                af[mi][1] = __float_as_uint(ap[8 * AST]);
                af[mi][2] = __float_as_uint(ap[4]);
                af[mi][3] = __float_as_uint(ap[8 * AST + 4]);
            }
            uint32_t bf[8][2];
#pragma unroll
            for (int ni = 0; ni < 8; ni++) {
                uint2 bv = *(const uint2*)(Bs + ((ks * BN + wn * 64 + ni * 8 + q) * 8 + cc * 2));
                bf[ni][0] = bv.x; bf[ni][1] = bv.y;
            }
#pragma unroll
            for (int mi = 0; mi < 4; mi++)
#pragma unroll
                for (int ni = 0; ni < 8; ni++)
                    MMA_TF32(acc[mi][ni], af[mi][0], af[mi][1], af[mi][2], af[mi][3],
                             bf[ni][0], bf[ni][1]);
        }
    }

    // ---- fused epilogue ----
    const int rBase = (int)mBase + wm * 64;
    const int cBase = nBase + wn * 64;

    float dA[4][2], dmA[4][2];
    if (FLAGS & F_LNA) {
#pragma unroll
        for (int mi = 0; mi < 4; mi++)
#pragma unroll
            for (int h = 0; h < 2; h++) {
                long row = rBase + mi * 16 + q + 8 * h;
                float2 r = rs[row * rsStride];
                float mean = r.x * invC;
                float var  = r.y * invC - mean * mean;
                float d = rsqrtf(var + 1e-5f);
                dA[mi][h] = d; dmA[mi][h] = d * mean;
            }
    }
    float sS[4][2], sS2[4][2];
    if (FLAGS & F_STAT) {
#pragma unroll
        for (int mi = 0; mi < 4; mi++)
#pragma unroll
            for (int h = 0; h < 2; h++) { sS[mi][h] = 0.f; sS2[mi][h] = 0.f; }
    }

#pragma unroll
    for (int mi = 0; mi < 4; mi++) {
#pragma unroll
        for (int ni = 0; ni < 8; ni++) {
            int c = cBase + ni * 8 + cc * 2;
            float b0 = bias[c], b1 = bias[c + 1];
            if (FLAGS & F_B2) { b0 += bias2[c]; b1 += bias2[c + 1]; }
            float w10 = 0.f, w11 = 0.f, w20 = 0.f, w21 = 0.f;
            if (FLAGS & F_LNA) {
                w10 = v1[c]; w11 = v1[c + 1];
                w20 = v2[c]; w21 = v2[c + 1];
            }
#pragma unroll
            for (int h = 0; h < 2; h++) {
                long row = rBase + mi * 16 + q + 8 * h;
                float v0, vv1;
                if (FLAGS & F_LNA) {
                    v0  = dA[mi][h] * acc[mi][ni][2 * h + 0] - dmA[mi][h] * w10 + w20 + b0;
                    vv1 = dA[mi][h] * acc[mi][ni][2 * h + 1] - dmA[mi][h] * w11 + w21 + b1;
                } else {
                    v0  = acc[mi][ni][2 * h + 0] + b0;
                    vv1 = acc[mi][ni][2 * h + 1] + b1;
                }
                if (FLAGS & F_GELU) { v0 = gelu_exact(v0); vv1 = gelu_exact(vv1); }
                long idx = row * ldc + c;
                if (FLAGS & F_RES) {
                    float2 rr = *(const float2*)(resb + idx);
                    v0 += rr.x; vv1 += rr.y;
                }
                *(float2*)(C + idx) = make_float2(v0, vv1);
                if (FLAGS & F_STAT) {
                    sS[mi][h]  += v0 + vv1;
                    sS2[mi][h] += v0 * v0 + vv1 * vv1;
                }
            }
        }
    }

    if (FLAGS & F_STAT) {
#pragma unroll
        for (int mi = 0; mi < 4; mi++)
#pragma unroll
            for (int h = 0; h < 2; h++) {
                float s = sS[mi][h], s2 = sS2[mi][h];
                s  += __shfl_xor_sync(0xffffffffu, s, 1);
                s2 += __shfl_xor_sync(0xffffffffu, s2, 1);
                s  += __shfl_xor_sync(0xffffffffu, s, 2);
                s2 += __shfl_xor_sync(0xffffffffu, s2, 2);
                if (cc == 0) {
                    long row = rBase + mi * 16 + q + 8 * h;
                    float* p = (float*)&stat[row * statStride];
                    atomicAdd(p, s);
                    atomicAdd(p + 1, s2);
                }
            }
    }
}

// ---------------------------------------------------------------------------
// SMALL GEMM (wh2) — R12-proven
// ---------------------------------------------------------------------------
template<int FLAGS>
__global__ void __launch_bounds__(THREADS, 2) gemm_sm(
    const float* __restrict__ A, int lda, long sA,
    const float* __restrict__ B, int ldbN, long sB,
    float* __restrict__ C, int ldc, long sC,
    int K,
    const float* __restrict__ bias, int sBias,
    const float2* __restrict__ rs, int rsStride, long rsZ, float invC,
    const float* __restrict__ v1, const float* __restrict__ v2, long vZ)
{
    extern __shared__ float sm[];
    const int tid  = threadIdx.x;
    const int lane = tid & 31;
    const int warp = tid >> 5;
    const int wm = warp & 3;
    const int wn = warp >> 2;
    const int q  = lane >> 2, cc = lane & 3;

    const int z = blockIdx.z;
    A    += (long)z * sA;
    B    += (long)z * sB;
    C    += (long)z * sC;
    bias += (long)z * sBias;
    if (FLAGS & F_LNA) { rs += (long)z * rsZ; v1 += (long)z * vZ; v2 += (long)z * vZ; }

    const long mBase = (long)blockIdx.y * BM;
    const int  nBase = blockIdx.x * SBN;
    const float* Ag = A + mBase * lda;

    const int numK = K / BK;

    float4 fA[4];
    auto ldgA = [&](int kt) {
#pragma unroll
        for (int i = 0; i < 4; i++) {
            int f = i * THREADS + tid;
            int r = f >> 3, c = (f & 7) * 4;
            fA[i] = *(const float4*)(Ag + (long)r * lda + kt * BK + c);
        }
    };
    auto stsA = [&](int buf) {
        float* As = sm + buf * SSTAGE;
#pragma unroll
        for (int i = 0; i < 4; i++) {
            int f = i * THREADS + tid;
            int r = f >> 3, c = (f & 7) * 4;
            float4 v = fA[i];
            *(uint4*)(As + r * AST + c) =
                make_uint4(f2tf32(v.x), f2tf32(v.y), f2tf32(v.z), f2tf32(v.w));
        }
    };
    auto cpB = [&](int kt, int buf) {
        float* Bs = sm + buf * SSTAGE + A_STAGE;
#pragma unroll
        for (int i = 0; i < 4; i++) {
            int idx = i * THREADS + tid;
            int half = idx & 1;
            int n = (idx >> 1) & 127;
            int g = idx >> 8;
            const float* src = B + ((long)(kt * 4 + g) * ldbN + nBase + n) * 8 + half * 4;
            cp16(Bs + (g * SBN + n) * 8 + half * 4, src);
        }
    };

    float acc[2][8][4];
#pragma unroll
    for (int a = 0; a < 2; a++)
#pragma unroll
        for (int b = 0; b < 8; b++)
#pragma unroll
            for (int c = 0; c < 4; c++) acc[a][b][c] = 0.f;

    ldgA(0); stsA(0); cpB(0, 0);
    asm volatile("cp.async.commit_group;\n" ::: "memory");

    for (int kt = 0; kt < numK; kt++) {
        asm volatile("cp.async.wait_group 0;\n" ::: "memory");
        __syncthreads();

        if (kt + 1 < numK) {
            ldgA(kt + 1);
            cpB(kt + 1, (kt + 1) & 1);
            asm volatile("cp.async.commit_group;\n" ::: "memory");
        }

        const float* As = sm + (kt & 1) * SSTAGE + (wm * 32) * AST;
        const float* Bs = sm + (kt & 1) * SSTAGE + A_STAGE;

#pragma unroll
        for (int ks = 0; ks < 4; ks++) {
            uint32_t af[2][4];
#pragma unroll
            for (int mi = 0; mi < 2; mi++) {
                const float* ap = As + (mi * 16 + q) * AST + ks * 8 + cc;
                af[mi][0] = __float_as_uint(ap[0]);
                af[mi][1] = __float_as_uint(ap[8 * AST]);
                af[mi][2] = __float_as_uint(ap[4]);
                af[mi][3] = __float_as_uint(ap[8 * AST + 4]);
            }
            uint32_t bf[8][2];
#pragma unroll
            for (int ni = 0; ni < 8; ni++) {
                uint2 bv = *(const uint2*)(Bs + ((ks * SBN + wn * 64 + ni * 8 + q) * 8 + cc * 2));
                bf[ni][0] = bv.x; bf[ni][1] = bv.y;
            }
#pragma unroll
            for (int mi = 0; mi < 2; mi++)
#pragma unroll
                for (int ni = 0; ni < 8; ni++)
                    MMA_TF32(acc[mi][ni], af[mi][0], af[mi][1], af[mi][2], af[mi][3],
                             bf[ni][0], bf[ni][1]);
        }

        if (kt + 1 < numK) stsA((kt + 1) & 1);
    }

    const int rBase = (int)mBase + wm * 32;
    const int cBase = nBase + wn * 64;

    float dA[2][2], dmA[2][2];
    if (FLAGS & F_LNA) {
#pragma unroll
        for (int mi = 0; mi < 2; mi++)
#pragma unroll
            for (int h = 0; h < 2; h++) {
                long row = rBase + mi * 16 + q + 8 * h;
                float2 r = rs[row * rsStride];
                float mean = r.x * invC;
                float var  = r.y * invC - mean * mean;
                float d = rsqrtf(var + 1e-5f);
                dA[mi][h] = d; dmA[mi][h] = d * mean;
            }
    }

#pragma unroll
    for (int mi = 0; mi < 2; mi++) {
#pragma unroll
        for (int ni = 0; ni < 8; ni++) {
            int c = cBase + ni * 8 + cc * 2;
            float b0 = bias[c], b1 = bias[c + 1];
            float w10 = 0.f, w11 = 0.f, w20 = 0.f, w21 = 0.f;
            if (FLAGS & F_LNA) {
                w10 = v1[c]; w11 = v1[c + 1];
                w20 = v2[c]; w21 = v2[c + 1];
            }
#pragma unroll
            for (int h = 0; h < 2; h++) {
                long row = rBase + mi * 16 + q + 8 * h;
                float v0, vv1;
                if (FLAGS & F_LNA) {
                    v0  = dA[mi][h] * acc[mi][ni][2 * h + 0] - dmA[mi][h] * w10 + w20 + b0;
                    vv1 = dA[mi][h] * acc[mi][ni][2 * h + 1] - dmA[mi][h] * w11 + w21 + b1;
                } else {
                    v0  = acc[mi][ni][2 * h + 0] + b0;
                    vv1 = acc[mi][ni][2 * h + 1] + b1;
                }
                if (FLAGS & F_GELU) { v0 = gelu_exact(v0); vv1 = gelu_exact(vv1); }
                long idx = row * ldc + c;
                *(float2*)(C + idx) = make_float2(v0, vv1);
            }
        }
    }
}

// ---------------------------------------------------------------------------
// foldgemm (R12-proven): writes fold product directly in packed stacked layout
// ---------------------------------------------------------------------------
__global__ void __launch_bounds__(THREADS, 2) foldgemm(
    const float* __restrict__ A0, const float* __restrict__ A1,
    const float* __restrict__ Bp, float* __restrict__ outP)
{
    extern __shared__ float sm[];
    const int tid  = threadIdx.x;
    const int lane = tid & 31;
    const int warp = tid >> 5;
    const int wm = warp & 3;
    const int wn = warp >> 2;
    const int q  = lane >> 2, cc = lane & 3;
    const int z = blockIdx.z;

    const float* A = z ? A1 : A0;
    const float* B = Bp + (long)z * DMODEL * DMODEL;
    const int K = DMODEL, lda = DMODEL, ldbN = DMODEL;

    const long mBase = (long)blockIdx.y * BM;
    const int  nBase = blockIdx.x * SBN;
    const float* Ag = A + mBase * lda;
    const int numK = K / BK;

    float4 fA[4];
    auto ldgA = [&](int kt) {
#pragma unroll
        for (int i = 0; i < 4; i++) {
            int f = i * THREADS + tid;
            int r = f >> 3, c = (f & 7) * 4;
            fA[i] = *(const float4*)(Ag + (long)r * lda + kt * BK + c);
        }
    };
    auto stsA = [&](int buf) {
        float* As = sm + buf * SSTAGE;
#pragma unroll
        for (int i = 0; i < 4; i++) {
            int f = i * THREADS + tid;
            int r = f >> 3, c = (f & 7) * 4;
            float4 v = fA[i];
            *(uint4*)(As + r * AST + c) =
                make_uint4(f2tf32(v.x), f2tf32(v.y), f2tf32(v.z), f2tf32(v.w));
        }
    };
    auto cpB = [&](int kt, int buf) {
        float* Bs = sm + buf * SSTAGE + A_STAGE;
#pragma unroll
        for (int i = 0; i < 4; i++) {
            int idx = i * THREADS + tid;
            int half = idx & 1;
            int n = (idx >> 1) & 127;
            int g = idx >> 8;
            const float* src = B + ((long)(kt * 4 + g) * ldbN + nBase + n) * 8 + half * 4;
            cp16(Bs + (g * SBN + n) * 8 + half * 4, src);
        }
    };

    float acc[2][8][4];
#pragma unroll
    for (int a = 0; a < 2; a++)
#pragma unroll
        for (int b = 0; b < 8; b++)
#pragma unroll
            for (int c = 0; c < 4; c++) acc[a][b][c] = 0.f;

    ldgA(0); stsA(0); cpB(0, 0);
    asm volatile("cp.async.commit_group;\n" ::: "memory");

    for (int kt = 0; kt < numK; kt++) {
        asm volatile("cp.async.wait_group 0;\n" ::: "memory");
        __syncthreads();
        if (kt + 1 < numK) {
            ldgA(kt + 1);
            cpB(kt + 1, (kt + 1) & 1);
            asm volatile("cp.async.commit_group;\n" ::: "memory");
        }
        const float* As = sm + (kt & 1) * SSTAGE + (wm * 32) * AST;
        const float* Bs = sm + (kt & 1) * SSTAGE + A_STAGE;
#pragma unroll
        for (int ks = 0; ks < 4; ks++) {
            uint32_t af[2][4];
#pragma unroll
            for (int mi = 0; mi < 2; mi++) {
                const float* ap = As + (mi * 16 + q) * AST + ks * 8 + cc;
                af[mi][0] = __float_as_uint(ap[0]);
                af[mi][1] = __float_as_uint(ap[8 * AST]);
                af[mi][2] = __float_as_uint(ap[4]);
                af[mi][3] = __float_as_uint(ap[8 * AST + 4]);
            }
            uint32_t bf[8][2];
#pragma unroll
            for (int ni = 0; ni < 8; ni++) {
                uint2 bv = *(const uint2*)(Bs + ((ks * SBN + wn * 64 + ni * 8 + q) * 8 + cc * 2));
                bf[ni][0] = bv.x; bf[ni][1] = bv.y;
            }
#pragma unroll
            for (int mi = 0; mi < 2; mi++)
#pragma unroll
                for (int ni = 0; ni < 8; ni++)
                    MMA_TF32(acc[mi][ni], af[mi][0], af[mi][1], af[mi][2], af[mi][3],
                             bf[ni][0], bf[ni][1]);
        }
        if (kt + 1 < numK) stsA((kt + 1) & 1);
    }

    const int rBase = (int)mBase + wm * 32;
    const int cBase = nBase + wn * 64;
#pragma unroll
    for (int mi = 0; mi < 2; mi++) {
#pragma unroll
        for (int ni = 0; ni < 8; ni++) {
            int c = cBase + ni * 8 + cc * 2;
#pragma unroll
            for (int h = 0; h < 2; h++) {
                int row = rBase + mi * 16 + q + 8 * h;
                int k = z * DMODEL + row;
                int pos = (row & 3) * 2 + ((row >> 2) & 1);
                long base = ((long)(k >> 3) * DMODEL) * 8 + pos;
                outP[base + (long)c * 8]       = __uint_as_float(f2tf32(acc[mi][ni][2 * h + 0]));
                outP[base + (long)(c + 1) * 8] = __uint_as_float(f2tf32(acc[mi][ni][2 * h + 1]));
            }
        }
    }
}

// ---------------------------------------------------------------------------
// Fused pre-pass helpers
// ---------------------------------------------------------------------------
static __device__ __forceinline__ void pack_dev(
    const float* __restrict__ in, float* __restrict__ out,
    int K, int N, const float* __restrict__ scale, long scaleZ,
    int nb, int kg, int z)
{
    const long zo = (long)z * K * N;
    const int n = nb * 128 + threadIdx.x;
    const float* sc = scale ? scale + (long)z * scaleZ + kg * 8 : nullptr;
    float v[8];
#pragma unroll
    for (int k = 0; k < 8; k++) {
        v[k] = in[zo + (long)(kg * 8 + k) * N + n];
        if (scale) v[k] *= sc[k];
    }
    float* o = out + zo + ((long)kg * N + n) * 8;
    *(uint4*)(o)     = make_uint4(f2tf32(v[0]), f2tf32(v[4]), f2tf32(v[1]), f2tf32(v[5]));
    *(uint4*)(o + 4) = make_uint4(f2tf32(v[2]), f2tf32(v[6]), f2tf32(v[3]), f2tf32(v[7]));
}

// full-K (non-atomic) vfold: v1[n] = sum_k g[k]W[k,n]; v2[n] = sum_k b[k]W[k,n]
static __device__ __forceinline__ void vfoldF_dev(
    const float* __restrict__ W, const float* __restrict__ g, const float* __restrict__ b,
    float* __restrict__ v1, float* __restrict__ v2,
    int K, int N, long gZ, long vZ, int nb, int z)
{
    const long zo = (long)z * K * N;
    const float* gg = g + (long)z * gZ;
    const float* bb = b + (long)z * gZ;
    const int n = nb * 128 + threadIdx.x;
    float s1a = 0.f, s1b = 0.f, s2a = 0.f, s2b = 0.f;
#pragma unroll 8
    for (int k = 0; k < K; k += 2) {
        float w0 = W[zo + (long)k * N + n];
        float w1 = W[zo + (long)(k + 1) * N + n];
        s1a += gg[k] * w0;     s1b += gg[k + 1] * w1;
        s2a += bb[k] * w0;     s2b += bb[k + 1] * w1;
    }
    v1[(long)z * vZ + n] = s1a + s1b;
    v2[(long)z * vZ + n] = s2a + s2b;
}

// ---------------------------------------------------------------------------
// prep_all: ONE launch for everything per-replay that isn't a main GEMM.
// Block ranges (total 5871):
//  [0,2048)    pack w_in
//  [2048,2304) pack wo_sa
//  [2304,2560) pack wo_ca
//  [2560,3584) pack ff1 (scale ln3_g)
//  [3584,4608) pack ff2
//  [4608,4992) pack wh1 x3 (scale lnout_g)
//  [4992,5664) pack wh2 x3 (scale lnh_g per head)
//  [5664,5668) bstk full-K (bo_sa+bo_ca + bv@Wo folds), non-atomic
//  [5668,5684) vfold ff1 full-K
//  [5684,5690) vfold h1 x3 full-K
//  [5690,5711) vfold h2 x3 full-K
//  [5711,5871) zero raw stat buffers (160 blocks x 512 floats, float4 stores)
// ---------------------------------------------------------------------------
__global__ void prep_all(
    const float* w_in, float* wp_in,
    const float* wo_sa, const float* wo_ca, float* wp_o,
    const float* w_ff1, float* wp_ff1, const float* ln3_g, const float* ln3_b,
    const float* w_ff2, float* wp_ff2,
    const float* wh1, float* wp_h1, const float* lnout_g, const float* lnout_b,
    const float* wh2, float* wp_h2, const float* lnh_g, const float* lnh_b,
    const float* bv_sa, const float* bv_ca,
    const float* bo_sa, const float* bo_ca, float* bstk,
    float* v1f, float* v2f, float* v1h1, float* v2h1, float* v1h2, float* v2h2,
    float* rs3, float* rsO, float* rsH)
{
    int bid = blockIdx.x;
    if (bid < 2048) { pack_dev(w_in, wp_in, DIN, DMODEL, nullptr, 0, bid & 3, bid >> 2, 0); return; }
    bid -= 2048;
    if (bid < 256) { pack_dev(wo_sa, wp_o, DMODEL, DMODEL, nullptr, 0, bid & 3, bid >> 2, 0); return; }
    bid -= 256;
    if (bid < 256) { pack_dev(wo_ca, wp_o + DMODEL * DMODEL, DMODEL, DMODEL, nullptr, 0, bid & 3, bid >> 2, 0); return; }
    bid -= 256;
    if (bid < 1024) { pack_dev(w_ff1, wp_ff1, DMODEL, FDIM, ln3_g, 0, bid & 15, bid >> 4, 0); return; }
    bid -= 1024;
    if (bid < 1024) { pack_dev(w_ff2, wp_ff2, FDIM, DMODEL, nullptr, 0, bid & 3, bid >> 2, 0); return; }
    bid -= 1024;
    if (bid < 384) { int l = bid & 127, z = bid >> 7;
        pack_dev(wh1, wp_h1, DMODEL, HD, lnout_g, 0, l & 1, l >> 1, z); return; }
    bid -= 384;
    if (bid < 672) { int l = bid % 224, z = bid / 224;
        pack_dev(wh2, wp_h2, HD, OUTD, lnh_g, HD, l % 7, l / 7, z); return; }
    bid -= 672;
    if (bid < 4) {
        // bstk[n] = bo_sa+bo_ca + sum_k bv_sa Wosa + bv_ca Woca   (full K)
        const int n = bid * 128 + threadIdx.x;
        float a0 = 0.f, a1 = 0.f;
#pragma unroll 8
        for (int k = 0; k < DMODEL; k += 2) {
            a0 += bv_sa[k]     * wo_sa[(long)k * DMODEL + n]
                + bv_ca[k]     * wo_ca[(long)k * DMODEL + n];
            a1 += bv_sa[k + 1] * wo_sa[(long)(k + 1) * DMODEL + n]
                + bv_ca[k + 1] * wo_ca[(long)(k + 1) * DMODEL + n];
        }
        bstk[n] = a0 + a1 + bo_sa[n] + bo_ca[n];
        return;
    }
    bid -= 4;
    if (bid < 16) { vfoldF_dev(w_ff1, ln3_g, ln3_b, v1f, v2f, DMODEL, FDIM, 0, 0, bid, 0); return; }
    bid -= 16;
    if (bid < 6) { vfoldF_dev(wh1, lnout_g, lnout_b, v1h1, v2h1, DMODEL, HD, 0, HD, bid & 1, bid >> 1); return; }
    bid -= 6;
    if (bid < 21) { vfoldF_dev(wh2, lnh_g, lnh_b, v1h2, v2h2, HD, OUTD, HD, OUTD, bid % 7, bid / 7); return; }
    bid -= 21;
    {
        // zero stat buffers: rs3 (16384 f) blocks 0-31, rsO blocks 32-63,
        // rsH (49152 f) blocks 64-159.  512 floats per block via float4.
        float* dst; int off;
        if (bid < 32)       { dst = rs3; off = bid * 512; }
        else if (bid < 64)  { dst = rsO; off = (bid - 32) * 512; }
        else                { dst = rsH; off = (bid - 64) * 512; }
        *(float4*)(dst + off + threadIdx.x * 4) = make_float4(0.f, 0.f, 0.f, 0.f);
    }
}

// ---------------------------------------------------------------------------
// lncat (R12-proven)
// ---------------------------------------------------------------------------
__global__ void lncat_kernel(const float* __restrict__ in, float* __restrict__ cat,
                             const float* __restrict__ g, const float* __restrict__ b)
{
    __shared__ float red[8];
    const int row = blockIdx.x;
    const float* x = in + (long)row * DMODEL;
    float* y = cat + (long)row * (2 * DMODEL);
    const int i = threadIdx.x * 4;

    float4 v = *(const float4*)(x + i);
    float s  = v.x + v.y + v.z + v.w;
    float s2 = v.x * v.x + v.y * v.y + v.z * v.z + v.w * v.w;
#pragma unroll
    for (int o = 16; o; o >>= 1) {
        s  += __shfl_xor_sync(0xffffffffu, s, o);
        s2 += __shfl_xor_sync(0xffffffffu, s2, o);
    }
    const int w = threadIdx.x >> 5;
    if ((threadIdx.x & 31) == 0) { red[w] = s; red[4 + w] = s2; }
    __syncthreads();
    if (threadIdx.x == 0) {
        float ts = 0.f, ts2 = 0.f;
#pragma unroll
        for (int j = 0; j < 4; j++) { ts += red[j]; ts2 += red[4 + j]; }
        red[0] = ts; red[4] = ts2;
    }
    __syncthreads();
    const float mean = red[0] / DMODEL;
    const float var  = red[4] / DMODEL - mean * mean;
    const float inv  = rsqrtf(var + 1e-5f);
    float4 gg = *(const float4*)(g + i);
    float4 bb = *(const float4*)(b + i);
    float4 o;
    o.x = (v.x - mean) * inv * gg.x + bb.x;
    o.y = (v.y - mean) * inv * gg.y + bb.y;
    o.z = (v.z - mean) * inv * gg.z + bb.z;
    o.w = (v.w - mean) * inv * gg.w + bb.w;
    *(float4*)(y + i) = o;
    *(float4*)(y + DMODEL + i) = v;
}

// ---------------------------------------------------------------------------
// Launch — 9 launches
// ---------------------------------------------------------------------------
extern "C" void kernel_launch(void* const* d_in, const int* in_sizes, int n_in,
                              void* d_out, int out_size)
{
    const float* x      = (const float*)d_in[0];
    const float* w_in   = (const float*)d_in[1];
    const float* b_in   = (const float*)d_in[2];
    const float* pos    = (const float*)d_in[3];
    const float* ln1_g  = (const float*)d_in[4];
    const float* ln1_b  = (const float*)d_in[5];
    const float* wv_sa  = (const float*)d_in[6];
    const float* bv_sa  = (const float*)d_in[7];
    const float* wo_sa  = (const float*)d_in[8];
    const float* bo_sa  = (const float*)d_in[9];
    const float* wv_ca  = (const float*)d_in[12];
    const float* bv_ca  = (const float*)d_in[13];
    const float* wo_ca  = (const float*)d_in[14];
    const float* bo_ca  = (const float*)d_in[15];
    const float* ln3_g  = (const float*)d_in[16];
    const float* ln3_b  = (const float*)d_in[17];
    const float* w_ff1  = (const float*)d_in[18];
    const float* b_ff1  = (const float*)d_in[19];
    const float* w_ff2  = (const float*)d_in[20];
    const float* b_ff2  = (const float*)d_in[21];
    const float* lnout_g= (const float*)d_in[22];
    const float* lnout_b= (const float*)d_in[23];
    const float* wh1    = (const float*)d_in[24];
    const float* bh1    = (const float*)d_in[25];
    const float* lnh_g  = (const float*)d_in[26];
    const float* lnh_b  = (const float*)d_in[27];
    const float* wh2    = (const float*)d_in[28];
    const float* bh2    = (const float*)d_in[29];
    float* out = (float*)d_out;

    float *h, *cat, *ff, *zz, *bstk;
    float *wp_in, *wp_o, *wp_stk, *wp_ff1, *wp_ff2, *wp_h1, *wp_h2;
    float *v1f, *v2f, *v1h1, *v2h1, *v1h2, *v2h2;
    float2 *rs3, *rsO, *rsH;
    cudaGetSymbolAddress((void**)&h,    g_h);
    cudaGetSymbolAddress((void**)&cat,  g_cat);
    cudaGetSymbolAddress((void**)&ff,   g_ff);
    cudaGetSymbolAddress((void**)&zz,   g_z);
    cudaGetSymbolAddress((void**)&bstk, g_bstk);
    cudaGetSymbolAddress((void**)&wp_in,  g_wp_in);
    cudaGetSymbolAddress((void**)&wp_o,   g_wp_o);
    cudaGetSymbolAddress((void**)&wp_stk, g_wp_stk);
    cudaGetSymbolAddress((void**)&wp_ff1, g_wp_ff1);
    cudaGetSymbolAddress((void**)&wp_ff2, g_wp_ff2);
    cudaGetSymbolAddress((void**)&wp_h1,  g_wp_h1);
    cudaGetSymbolAddress((void**)&wp_h2,  g_wp_h2);
    cudaGetSymbolAddress((void**)&v1f,  g_v1_ff1);
    cudaGetSymbolAddress((void**)&v2f,  g_v2_ff1);
    cudaGetSymbolAddress((void**)&v1h1, g_v1_h1);
    cudaGetSymbolAddress((void**)&v2h1, g_v2_h1);
    cudaGetSymbolAddress((void**)&v1h2, g_v1_h2);
    cudaGetSymbolAddress((void**)&v2h2, g_v2_h2);
    cudaGetSymbolAddress((void**)&rs3, g_rs_ln3);
    cudaGetSymbolAddress((void**)&rsO, g_rs_lout);
    cudaGetSymbolAddress((void**)&rsH, g_rs_lnh);

    cudaFuncSetAttribute(gemm_big<F_B2>,            cudaFuncAttributeMaxDynamicSharedMemorySize, SMB_BIG);
    cudaFuncSetAttribute(gemm_big<F_RES | F_STAT>,  cudaFuncAttributeMaxDynamicSharedMemorySize, SMB_BIG);
    cudaFuncSetAttribute(gemm_big<F_LNA | F_GELU>,  cudaFuncAttributeMaxDynamicSharedMemorySize, SMB_BIG);
    cudaFuncSetAttribute(gemm_big<F_LNA | F_GELU | F_STAT>, cudaFuncAttributeMaxDynamicSharedMemorySize, SMB_BIG);
    cudaFuncSetAttribute(gemm_sm<F_LNA>,            cudaFuncAttributeMaxDynamicSharedMemorySize, SMB_SM);
    cudaFuncSetAttribute(foldgemm,                  cudaFuncAttributeMaxDynamicSharedMemorySize, SMB_SM);

    const int MG = BATCH / BM;  // 64
    const float invD = 1.f / DMODEL, invH = 1.f / HD;

    // [0] all packs + full-K folds + stat zeroing (one launch)
    prep_all<<<5871, 128>>>(
        w_in, wp_in, wo_sa, wo_ca, wp_o,
        w_ff1, wp_ff1, ln3_g, ln3_b, w_ff2, wp_ff2,
        wh1, wp_h1, lnout_g, lnout_b, wh2, wp_h2, lnh_g, lnh_b,
        bv_sa, bv_ca, bo_sa, bo_ca, bstk,
        v1f, v2f, v1h1, v2h1, v1h2, v2h2,
        (float*)rs3, (float*)rsO, (float*)rsH);
    // [1] attention folds -> packed stacked weight (K=1024)
    foldgemm<<<dim3(DMODEL / SBN, DMODEL / BM, 2), THREADS, SMB_SM>>>(wv_sa, wv_ca, wp_o, wp_stk);
    // [2] gemm1: h = x @ w_in + b_in + pos
    gemm_big<F_B2><<<dim3(DMODEL / BN, MG, 1), THREADS, SMB_BIG>>>(
        x, DIN, 0, wp_in, DMODEL, 0, h, DMODEL, 0, DIN, b_in, 0, pos, nullptr,
        nullptr, 0, 0.f, nullptr, nullptr, 0, nullptr, 0, 0);
    // [3] cat = [ln1(h) | h]
    lncat_kernel<<<BATCH, 128>>>(h, cat, ln1_g, ln1_b);
    // [4] h = h + cat @ Wstk + bstk ; accumulate ln3 stats
    gemm_big<F_RES | F_STAT><<<dim3(DMODEL / BN, MG, 1), THREADS, SMB_BIG>>>(
        cat, 2 * DMODEL, 0, wp_stk, DMODEL, 0, h, DMODEL, 0, 2 * DMODEL,
        bstk, 0, nullptr, h, nullptr, 0, 0.f, nullptr, nullptr, 0, rs3, 1, 0);
    // [5] ff = gelu(ln3(h) @ w_ff1 + b_ff1)   [LN from raw stats]
    gemm_big<F_LNA | F_GELU><<<dim3(FDIM / BN, MG, 1), THREADS, SMB_BIG>>>(
        h, DMODEL, 0, wp_ff1, FDIM, 0, ff, FDIM, 0, DMODEL, b_ff1, 0, nullptr, nullptr,
        rs3, 1, invD, v1f, v2f, 0, nullptr, 0, 0);
    // [6] h = h + ff @ w_ff2 + b_ff2 ; accumulate lnout stats
    gemm_big<F_RES | F_STAT><<<dim3(DMODEL / BN, MG, 1), THREADS, SMB_BIG>>>(
        ff, FDIM, 0, wp_ff2, DMODEL, 0, h, DMODEL, 0, FDIM, b_ff2, 0, nullptr, h,
        nullptr, 0, 0.f, nullptr, nullptr, 0, rsO, 1, 0);
    // [7] zz = gelu(lnout(h) @ wh1 + bh1) ; accumulate lnh stats
    gemm_big<F_LNA | F_GELU | F_STAT><<<dim3(HD / BN, MG, NH), THREADS, SMB_BIG>>>(
        h, DMODEL, 0, wp_h1, HD, (long)DMODEL * HD, zz, NH * HD, HD,
        DMODEL, bh1, HD, nullptr, nullptr, rsO, 1, invD, v1h1, v2h1, HD,
        rsH, NH, 1);
    // [8] out = ln_head(zz) @ wh2 + bh2
    gemm_sm<F_LNA><<<dim3(OUTD / SBN, MG, NH), THREADS, SMB_SM>>>(
        zz, NH * HD, HD, wp_h2, OUTD, (long)HD * OUTD, out, NH * OUTD, OUTD,
        HD, bh2, OUTD, rsH, NH, 1, invH, v1h2, v2h2, OUTD);
}

// round 16
// speedup vs baseline: 1.0861x; 1.0861x over previous
#include <cuda_runtime.h>
#include <math.h>
#include <stdint.h>

// ---------------------------------------------------------------------------
// Shapes
// ---------------------------------------------------------------------------
#define BATCH  8192
#define DIN    4096
#define DMODEL 512
#define FDIM   2048
#define NH     3
#define HD     256
#define OUTD   896

// big GEMM tile (128x256, 8 warps of 64x64), BK=32, 3-stage  (R12 proven)
#define BM 128
#define BN 256
#define BK 32
#define THREADS 256
#define AST 36
#define A_STAGE (BM * AST)
#define B_STAGE (4 * BN * 8)
#define STAGE (A_STAGE + B_STAGE)
#define SMB_BIG (3 * STAGE * 4)            // 153600 B

// small GEMM tile (128x128, 8 warps of 32x64), BK=32, 2-stage, 2 CTA/SM
#define SBN 128
#define SSTAGE (A_STAGE + 4 * SBN * 8)
#define SMB_SM (2 * SSTAGE * 4)            // 69632 B

// Epilogue flags
#define F_B2     1
#define F_GELU   2
#define F_RES    4
#define F_LNA    8
#define F_STAT   16
#define F_SPLITA 32   // A split: first K/2 tiles from A, second K/2 from A2 (same lda)

// ---------------------------------------------------------------------------
// Scratch
// ---------------------------------------------------------------------------
__device__ float g_h  [BATCH * DMODEL];
__device__ float g_cat[BATCH * DMODEL];           // LN half only (split-A)
__device__ float g_ff [BATCH * FDIM];
__device__ float g_z  [BATCH * NH * HD];

__device__ float g_wp_in [DIN * DMODEL];
__device__ float g_wp_o  [2 * DMODEL * DMODEL];
__device__ float g_wp_stk[2 * DMODEL * DMODEL];
__device__ float g_wp_ff1[DMODEL * FDIM];
__device__ float g_wp_ff2[FDIM * DMODEL];
__device__ float g_wp_h1 [NH * DMODEL * HD];
__device__ float g_wp_h2 [NH * HD * OUTD];

__device__ float g_bstk[DMODEL];

__device__ float g_v1_ff1[FDIM];
__device__ float g_v2_ff1[FDIM];
__device__ float g_v1_h1 [NH * HD];
__device__ float g_v2_h1 [NH * HD];
__device__ float g_v1_h2 [NH * OUTD];
__device__ float g_v2_h2 [NH * OUTD];

// raw row stats {sum, sumsq}
__device__ float2 g_rs_ln3 [BATCH];
__device__ float2 g_rs_lout[BATCH];
__device__ float2 g_rs_lnh [BATCH * NH];

// ---------------------------------------------------------------------------
// Helpers
// ---------------------------------------------------------------------------
static __device__ __forceinline__ void cp16(float* sm, const float* gm) {
    unsigned s = (unsigned)__cvta_generic_to_shared(sm);
    asm volatile("cp.async.ca.shared.global [%0], [%1], 16;\n" :: "r"(s), "l"(gm));
}
static __device__ __forceinline__ unsigned f2tf32(float f) {
    unsigned u;
    asm("cvt.rna.tf32.f32 %0, %1;" : "=r"(u) : "f"(f));
    return u;
}
static __device__ __forceinline__ float gelu_exact(float v) {
    return 0.5f * v * (1.0f + erff(v * 0.70710678118654752f));
}
#define MMA_TF32(acc, a0, a1, a2, a3, b0, b1)                                  \
    asm volatile(                                                              \
        "mma.sync.aligned.m16n8k8.row.col.f32.tf32.tf32.f32 "                  \
        "{%0,%1,%2,%3},{%4,%5,%6,%7},{%8,%9},{%0,%1,%2,%3};\n"                 \
        : "+f"((acc)[0]), "+f"((acc)[1]), "+f"((acc)[2]), "+f"((acc)[3])       \
        : "r"(a0), "r"(a1), "r"(a2), "r"(a3), "r"(b0), "r"(b1))

// ---------------------------------------------------------------------------
// BIG GEMM (R12-proven; only addition: F_SPLITA source select in ldgA)
// ---------------------------------------------------------------------------
template<int FLAGS>
__global__ void __launch_bounds__(THREADS, 1) gemm_big(
    const float* __restrict__ A, int lda, long sA,
    const float* __restrict__ B, int ldbN, long sB,
    float* __restrict__ C, int ldc, long sC,
    int K,
    const float* __restrict__ bias, int sBias,
    const float* __restrict__ bias2,
    const float* __restrict__ res,
    const float2* __restrict__ rs, int rsStride, float invC,
    const float* __restrict__ v1, const float* __restrict__ v2, long vZ,
    float2* __restrict__ stat, int statStride, int statZ,
    const float* __restrict__ A2)
{
    extern __shared__ float sm[];
    const int tid  = threadIdx.x;
    const int lane = tid & 31;
    const int warp = tid >> 5;
    const int wm = warp & 1;
    const int wn = warp >> 1;
    const int q  = lane >> 2, cc = lane & 3;

    const int z = blockIdx.z;
    A    += (long)z * sA;
    B    += (long)z * sB;
    C    += (long)z * sC;
    bias += (long)z * sBias;
    const float* resb = (FLAGS & F_RES) ? (res + (long)z * sC) : nullptr;
    if (FLAGS & F_LNA) { v1 += (long)z * vZ; v2 += (long)z * vZ; }
    if (FLAGS & F_STAT) stat += (long)z * statZ;

    const long mBase = (long)blockIdx.y * BM;
    const int  nBase = blockIdx.x * BN;
    const float* Ag  = A + mBase * lda;
    const float* Ag2 = (FLAGS & F_SPLITA) ? (A2 + mBase * lda) : nullptr;

    const int numK = K / BK;
    const int halfK = numK >> 1;

    float4 fA[4];
    auto ldgA = [&](int kt) {
        const float* src = Ag;
        int kk = kt;
        if (FLAGS & F_SPLITA) {
            if (kt >= halfK) { src = Ag2; kk = kt - halfK; }
        }
#pragma unroll
        for (int i = 0; i < 4; i++) {
            int f = i * THREADS + tid;
            int r = f >> 3, c = (f & 7) * 4;
            fA[i] = *(const float4*)(src + (long)r * lda + kk * BK + c);
        }
    };
    auto stsA = [&](int stg) {
        float* As = sm + stg * STAGE;
#pragma unroll
        for (int i = 0; i < 4; i++) {
            int f = i * THREADS + tid;
            int r = f >> 3, c = (f & 7) * 4;
            float4 v = fA[i];
            *(uint4*)(As + r * AST + c) =
                make_uint4(f2tf32(v.x), f2tf32(v.y), f2tf32(v.z), f2tf32(v.w));
        }
    };
    auto cpB = [&](int kt, int stg) {
        float* Bs = sm + stg * STAGE + A_STAGE;
#pragma unroll
        for (int i = 0; i < 8; i++) {
            int idx = i * THREADS + tid;
            int half = idx & 1;
            int n = (idx >> 1) & 255;
            int g = idx >> 9;
            const float* src = B + ((long)(kt * 4 + g) * ldbN + nBase + n) * 8 + half * 4;
            cp16(Bs + (g * BN + n) * 8 + half * 4, src);
        }
    };

    float acc[4][8][4];
#pragma unroll
    for (int a = 0; a < 4; a++)
#pragma unroll
        for (int b = 0; b < 8; b++)
#pragma unroll
            for (int c = 0; c < 4; c++) acc[a][b][c] = 0.f;

    ldgA(0); stsA(0);
    cpB(0, 0);
    asm volatile("cp.async.commit_group;\n" ::: "memory");
    ldgA(1);
    cpB(1, 1);
    asm volatile("cp.async.commit_group;\n" ::: "memory");

    for (int kt = 0; kt < numK; kt++) {
        asm volatile("cp.async.wait_group 1;\n" ::: "memory");
        __syncthreads();

        if (kt + 1 < numK) stsA((kt + 1) % 3);
        if (kt + 2 < numK) { ldgA(kt + 2); cpB(kt + 2, (kt + 2) % 3); }
        asm volatile("cp.async.commit_group;\n" ::: "memory");

        const float* As = sm + (kt % 3) * STAGE + (wm * 64) * AST;
        const float* Bs = sm + (kt % 3) * STAGE + A_STAGE;

#pragma unroll
        for (int ks = 0; ks < 4; ks++) {
            uint32_t af[4][4];
#pragma unroll
            for (int mi = 0; mi < 4; mi++) {
                const float* ap = As + (mi * 16 + q) * AST + ks * 8 + cc;
                af[mi][0] = __float_as_uint(ap[0]);
                af[mi][1] = __float_as_uint(ap[8 * AST]);
                af[mi][2] = __float_as_uint(ap[4]);
                af[mi][3] = __float_as_uint(ap[8 * AST + 4]);
            }
            uint32_t bf[8][2];
#pragma unroll
            for (int ni = 0; ni < 8; ni++) {
                uint2 bv = *(const uint2*)(Bs + ((ks * BN + wn * 64 + ni * 8 + q) * 8 + cc * 2));
                bf[ni][0] = bv.x; bf[ni][1] = bv.y;
            }
#pragma unroll
            for (int mi = 0; mi < 4; mi++)
#pragma unroll
                for (int ni = 0; ni < 8; ni++)
                    MMA_TF32(acc[mi][ni], af[mi][0], af[mi][1], af[mi][2], af[mi][3],
                             bf[ni][0], bf[ni][1]);
        }
    }

    // ---- fused epilogue ----
    const int rBase = (int)mBase + wm * 64;
    const int cBase = nBase + wn * 64;

    float dA[4][2], dmA[4][2];
    if (FLAGS & F_LNA) {
#pragma unroll
        for (int mi = 0; mi < 4; mi++)
#pragma unroll
            for (int h = 0; h < 2; h++) {
                long row = rBase + mi * 16 + q + 8 * h;
                float2 r = rs[row * rsStride];
                float mean = r.x * invC;
                float var  = r.y * invC - mean * mean;
                float d = rsqrtf(var + 1e-5f);
                dA[mi][h] = d; dmA[mi][h] = d * mean;
            }
    }
    float sS[4][2], sS2[4][2];
    if (FLAGS & F_STAT) {
#pragma unroll
        for (int mi = 0; mi < 4; mi++)
#pragma unroll
            for (int h = 0; h < 2; h++) { sS[mi][h] = 0.f; sS2[mi][h] = 0.f; }
    }

#pragma unroll
    for (int mi = 0; mi < 4; mi++) {
#pragma unroll
        for (int ni = 0; ni < 8; ni++) {
            int c = cBase + ni * 8 + cc * 2;
            float b0 = bias[c], b1 = bias[c + 1];
            if (FLAGS & F_B2) { b0 += bias2[c]; b1 += bias2[c + 1]; }
            float w10 = 0.f, w11 = 0.f, w20 = 0.f, w21 = 0.f;
            if (FLAGS & F_LNA) {
                w10 = v1[c]; w11 = v1[c + 1];
                w20 = v2[c]; w21 = v2[c + 1];
            }
#pragma unroll
            for (int h = 0; h < 2; h++) {
                long row = rBase + mi * 16 + q + 8 * h;
                float v0, vv1;
                if (FLAGS & F_LNA) {
                    v0  = dA[mi][h] * acc[mi][ni][2 * h + 0] - dmA[mi][h] * w10 + w20 + b0;
                    vv1 = dA[mi][h] * acc[mi][ni][2 * h + 1] - dmA[mi][h] * w11 + w21 + b1;
                } else {
                    v0  = acc[mi][ni][2 * h + 0] + b0;
                    vv1 = acc[mi][ni][2 * h + 1] + b1;
                }
                if (FLAGS & F_GELU) { v0 = gelu_exact(v0); vv1 = gelu_exact(vv1); }
                long idx = row * ldc + c;
                if (FLAGS & F_RES) {
                    float2 rr = *(const float2*)(resb + idx);
                    v0 += rr.x; vv1 += rr.y;
                }
                *(float2*)(C + idx) = make_float2(v0, vv1);
                if (FLAGS & F_STAT) {
                    sS[mi][h]  += v0 + vv1;
                    sS2[mi][h] += v0 * v0 + vv1 * vv1;
                }
            }
        }
    }

    if (FLAGS & F_STAT) {
#pragma unroll
        for (int mi = 0; mi < 4; mi++)
#pragma unroll
            for (int h = 0; h < 2; h++) {
                float s = sS[mi][h], s2 = sS2[mi][h];
                s  += __shfl_xor_sync(0xffffffffu, s, 1);
                s2 += __shfl_xor_sync(0xffffffffu, s2, 1);
                s  += __shfl_xor_sync(0xffffffffu, s, 2);
                s2 += __shfl_xor_sync(0xffffffffu, s2, 2);
                if (cc == 0) {
                    long row = rBase + mi * 16 + q + 8 * h;
                    float* p = (float*)&stat[row * statStride];
                    atomicAdd(p, s);
                    atomicAdd(p + 1, s2);
                }
            }
    }
}

// ---------------------------------------------------------------------------
// SMALL GEMM (wh2) — R12-proven
// ---------------------------------------------------------------------------
template<int FLAGS>
__global__ void __launch_bounds__(THREADS, 2) gemm_sm(
    const float* __restrict__ A, int lda, long sA,
    const float* __restrict__ B, int ldbN, long sB,
    float* __restrict__ C, int ldc, long sC,
    int K,
    const float* __restrict__ bias, int sBias,
    const float2* __restrict__ rs, int rsStride, long rsZ, float invC,
    const float* __restrict__ v1, const float* __restrict__ v2, long vZ)
{
    extern __shared__ float sm[];
    const int tid  = threadIdx.x;
    const int lane = tid & 31;
    const int warp = tid >> 5;
    const int wm = warp & 3;
    const int wn = warp >> 2;
    const int q  = lane >> 2, cc = lane & 3;

    const int z = blockIdx.z;
    A    += (long)z * sA;
    B    += (long)z * sB;
    C    += (long)z * sC;
    bias += (long)z * sBias;
    if (FLAGS & F_LNA) { rs += (long)z * rsZ; v1 += (long)z * vZ; v2 += (long)z * vZ; }

    const long mBase = (long)blockIdx.y * BM;
    const int  nBase = blockIdx.x * SBN;
    const float* Ag = A + mBase * lda;

    const int numK = K / BK;

    float4 fA[4];
    auto ldgA = [&](int kt) {
#pragma unroll
        for (int i = 0; i < 4; i++) {
            int f = i * THREADS + tid;
            int r = f >> 3, c = (f & 7) * 4;
            fA[i] = *(const float4*)(Ag + (long)r * lda + kt * BK + c);
        }
    };
    auto stsA = [&](int buf) {
        float* As = sm + buf * SSTAGE;
#pragma unroll
        for (int i = 0; i < 4; i++) {
            int f = i * THREADS + tid;
            int r = f >> 3, c = (f & 7) * 4;
            float4 v = fA[i];
            *(uint4*)(As + r * AST + c) =
                make_uint4(f2tf32(v.x), f2tf32(v.y), f2tf32(v.z), f2tf32(v.w));
        }
    };
    auto cpB = [&](int kt, int buf) {
        float* Bs = sm + buf * SSTAGE + A_STAGE;
#pragma unroll
        for (int i = 0; i < 4; i++) {
            int idx = i * THREADS + tid;
            int half = idx & 1;
            int n = (idx >> 1) & 127;
            int g = idx >> 8;
            const float* src = B + ((long)(kt * 4 + g) * ldbN + nBase + n) * 8 + half * 4;
            cp16(Bs + (g * SBN + n) * 8 + half * 4, src);
        }
    };

    float acc[2][8][4];
#pragma unroll
    for (int a = 0; a < 2; a++)
#pragma unroll
        for (int b = 0; b < 8; b++)
#pragma unroll
            for (int c = 0; c < 4; c++) acc[a][b][c] = 0.f;

    ldgA(0); stsA(0); cpB(0, 0);
    asm volatile("cp.async.commit_group;\n" ::: "memory");

    for (int kt = 0; kt < numK; kt++) {
        asm volatile("cp.async.wait_group 0;\n" ::: "memory");
        __syncthreads();

        if (kt + 1 < numK) {
            ldgA(kt + 1);
            cpB(kt + 1, (kt + 1) & 1);
            asm volatile("cp.async.commit_group;\n" ::: "memory");
        }

        const float* As = sm + (kt & 1) * SSTAGE + (wm * 32) * AST;
        const float* Bs = sm + (kt & 1) * SSTAGE + A_STAGE;

#pragma unroll
        for (int ks = 0; ks < 4; ks++) {
            uint32_t af[2][4];
#pragma unroll
            for (int mi = 0; mi < 2; mi++) {
                const float* ap = As + (mi * 16 + q) * AST + ks * 8 + cc;
                af[mi][0] = __float_as_uint(ap[0]);
                af[mi][1] = __float_as_uint(ap[8 * AST]);
                af[mi][2] = __float_as_uint(ap[4]);
                af[mi][3] = __float_as_uint(ap[8 * AST + 4]);
            }
            uint32_t bf[8][2];
#pragma unroll
            for (int ni = 0; ni < 8; ni++) {
                uint2 bv = *(const uint2*)(Bs + ((ks * SBN + wn * 64 + ni * 8 + q) * 8 + cc * 2));
                bf[ni][0] = bv.x; bf[ni][1] = bv.y;
            }
#pragma unroll
            for (int mi = 0; mi < 2; mi++)
#pragma unroll
                for (int ni = 0; ni < 8; ni++)
                    MMA_TF32(acc[mi][ni], af[mi][0], af[mi][1], af[mi][2], af[mi][3],
                             bf[ni][0], bf[ni][1]);
        }

        if (kt + 1 < numK) stsA((kt + 1) & 1);
    }

    const int rBase = (int)mBase + wm * 32;
    const int cBase = nBase + wn * 64;

    float dA[2][2], dmA[2][2];
    if (FLAGS & F_LNA) {
#pragma unroll
        for (int mi = 0; mi < 2; mi++)
#pragma unroll
            for (int h = 0; h < 2; h++) {
                long row = rBase + mi * 16 + q + 8 * h;
                float2 r = rs[row * rsStride];
                float mean = r.x * invC;
                float var  = r.y * invC - mean * mean;
                float d = rsqrtf(var + 1e-5f);
                dA[mi][h] = d; dmA[mi][h] = d * mean;
            }
    }

#pragma unroll
    for (int mi = 0; mi < 2; mi++) {
#pragma unroll
        for (int ni = 0; ni < 8; ni++) {
            int c = cBase + ni * 8 + cc * 2;
            float b0 = bias[c], b1 = bias[c + 1];
            float w10 = 0.f, w11 = 0.f, w20 = 0.f, w21 = 0.f;
            if (FLAGS & F_LNA) {
                w10 = v1[c]; w11 = v1[c + 1];
                w20 = v2[c]; w21 = v2[c + 1];
            }
#pragma unroll
            for (int h = 0; h < 2; h++) {
                long row = rBase + mi * 16 + q + 8 * h;
                float v0, vv1;
                if (FLAGS & F_LNA) {
                    v0  = dA[mi][h] * acc[mi][ni][2 * h + 0] - dmA[mi][h] * w10 + w20 + b0;
                    vv1 = dA[mi][h] * acc[mi][ni][2 * h + 1] - dmA[mi][h] * w11 + w21 + b1;
                } else {
                    v0  = acc[mi][ni][2 * h + 0] + b0;
                    vv1 = acc[mi][ni][2 * h + 1] + b1;
                }
                if (FLAGS & F_GELU) { v0 = gelu_exact(v0); vv1 = gelu_exact(vv1); }
                long idx = row * ldc + c;
                *(float2*)(C + idx) = make_float2(v0, vv1);
            }
        }
    }
}

// ---------------------------------------------------------------------------
// foldgemm (R12-proven): writes fold product directly in packed stacked layout
// ---------------------------------------------------------------------------
__global__ void __launch_bounds__(THREADS, 2) foldgemm(
    const float* __restrict__ A0, const float* __restrict__ A1,
    const float* __restrict__ Bp, float* __restrict__ outP)
{
    extern __shared__ float sm[];
    const int tid  = threadIdx.x;
    const int lane = tid & 31;
    const int warp = tid >> 5;
    const int wm = warp & 3;
    const int wn = warp >> 2;
    const int q  = lane >> 2, cc = lane & 3;
    const int z = blockIdx.z;

    const float* A = z ? A1 : A0;
    const float* B = Bp + (long)z * DMODEL * DMODEL;
    const int K = DMODEL, lda = DMODEL, ldbN = DMODEL;

    const long mBase = (long)blockIdx.y * BM;
    const int  nBase = blockIdx.x * SBN;
    const float* Ag = A + mBase * lda;
    const int numK = K / BK;

    float4 fA[4];
    auto ldgA = [&](int kt) {
#pragma unroll
        for (int i = 0; i < 4; i++) {
            int f = i * THREADS + tid;
            int r = f >> 3, c = (f & 7) * 4;
            fA[i] = *(const float4*)(Ag + (long)r * lda + kt * BK + c);
        }
    };
    auto stsA = [&](int buf) {
        float* As = sm + buf * SSTAGE;
#pragma unroll
        for (int i = 0; i < 4; i++) {
            int f = i * THREADS + tid;
            int r = f >> 3, c = (f & 7) * 4;
            float4 v = fA[i];
            *(uint4*)(As + r * AST + c) =
                make_uint4(f2tf32(v.x), f2tf32(v.y), f2tf32(v.z), f2tf32(v.w));
        }
    };
    auto cpB = [&](int kt, int buf) {
        float* Bs = sm + buf * SSTAGE + A_STAGE;
#pragma unroll
        for (int i = 0; i < 4; i++) {
            int idx = i * THREADS + tid;
            int half = idx & 1;
            int n = (idx >> 1) & 127;
            int g = idx >> 8;
            const float* src = B + ((long)(kt * 4 + g) * ldbN + nBase + n) * 8 + half * 4;
            cp16(Bs + (g * SBN + n) * 8 + half * 4, src);
        }
    };

    float acc[2][8][4];
#pragma unroll
    for (int a = 0; a < 2; a++)
#pragma unroll
        for (int b = 0; b < 8; b++)
#pragma unroll
            for (int c = 0; c < 4; c++) acc[a][b][c] = 0.f;

    ldgA(0); stsA(0); cpB(0, 0);
    asm volatile("cp.async.commit_group;\n" ::: "memory");

    for (int kt = 0; kt < numK; kt++) {
        asm volatile("cp.async.wait_group 0;\n" ::: "memory");
        __syncthreads();
        if (kt + 1 < numK) {
            ldgA(kt + 1);
            cpB(kt + 1, (kt + 1) & 1);
            asm volatile("cp.async.commit_group;\n" ::: "memory");
        }
        const float* As = sm + (kt & 1) * SSTAGE + (wm * 32) * AST;
        const float* Bs = sm + (kt & 1) * SSTAGE + A_STAGE;
#pragma unroll
        for (int ks = 0; ks < 4; ks++) {
            uint32_t af[2][4];
#pragma unroll
            for (int mi = 0; mi < 2; mi++) {
                const float* ap = As + (mi * 16 + q) * AST + ks * 8 + cc;
                af[mi][0] = __float_as_uint(ap[0]);
                af[mi][1] = __float_as_uint(ap[8 * AST]);
                af[mi][2] = __float_as_uint(ap[4]);
                af[mi][3] = __float_as_uint(ap[8 * AST + 4]);
            }
            uint32_t bf[8][2];
#pragma unroll
            for (int ni = 0; ni < 8; ni++) {
                uint2 bv = *(const uint2*)(Bs + ((ks * SBN + wn * 64 + ni * 8 + q) * 8 + cc * 2));
                bf[ni][0] = bv.x; bf[ni][1] = bv.y;
            }
#pragma unroll
            for (int mi = 0; mi < 2; mi++)
#pragma unroll
                for (int ni = 0; ni < 8; ni++)
                    MMA_TF32(acc[mi][ni], af[mi][0], af[mi][1], af[mi][2], af[mi][3],
                             bf[ni][0], bf[ni][1]);
        }
        if (kt + 1 < numK) stsA((kt + 1) & 1);
    }

    const int rBase = (int)mBase + wm * 32;
    const int cBase = nBase + wn * 64;
#pragma unroll
    for (int mi = 0; mi < 2; mi++) {
#pragma unroll
        for (int ni = 0; ni < 8; ni++) {
            int c = cBase + ni * 8 + cc * 2;
#pragma unroll
            for (int h = 0; h < 2; h++) {
                int row = rBase + mi * 16 + q + 8 * h;
                int k = z * DMODEL + row;
                int pos = (row & 3) * 2 + ((row >> 2) & 1);
                long base = ((long)(k >> 3) * DMODEL) * 8 + pos;
                outP[base + (long)c * 8]       = __uint_as_float(f2tf32(acc[mi][ni][2 * h + 0]));
                outP[base + (long)(c + 1) * 8] = __uint_as_float(f2tf32(acc[mi][ni][2 * h + 1]));
            }
        }
    }
}

// ---------------------------------------------------------------------------
// Fused pre-pass helpers (R12-proven)
// ---------------------------------------------------------------------------
static __device__ __forceinline__ void pack_dev(
    const float* __restrict__ in, float* __restrict__ out,
    int K, int N, const float* __restrict__ scale, long scaleZ,
    int nb, int kg, int z)
{
    const long zo = (long)z * K * N;
    const int n = nb * 128 + threadIdx.x;
    const float* sc = scale ? scale + (long)z * scaleZ + kg * 8 : nullptr;
    float v[8];
#pragma unroll
    for (int k = 0; k < 8; k++) {
        v[k] = in[zo + (long)(kg * 8 + k) * N + n];
        if (scale) v[k] *= sc[k];
    }
    float* o = out + zo + ((long)kg * N + n) * 8;
    *(uint4*)(o)     = make_uint4(f2tf32(v[0]), f2tf32(v[4]), f2tf32(v[1]), f2tf32(v[5]));
    *(uint4*)(o + 4) = make_uint4(f2tf32(v[2]), f2tf32(v[6]), f2tf32(v[3]), f2tf32(v[7]));
}

static __device__ __forceinline__ void vfold_dev(
    const float* __restrict__ W, const float* __restrict__ g, const float* __restrict__ b,
    float* __restrict__ v1, float* __restrict__ v2,
    int K, int N, long gZ, long vZ, int nb, int kseg, int z)
{
    const long zo = (long)z * K * N;
    const float* gg = g + (long)z * gZ;
    const float* bb = b + (long)z * gZ;
    const int n  = nb * 128 + threadIdx.x;
    const int k0 = kseg * 64;
    float s1 = 0.f, s2 = 0.f;
#pragma unroll 4
    for (int k = 0; k < 64; k++) {
        float w = W[zo + (long)(k0 + k) * N + n];
        s1 += gg[k0 + k] * w;
        s2 += bb[k0 + k] * w;
    }
    atomicAdd(v1 + (long)z * vZ + n, s1);
    atomicAdd(v2 + (long)z * vZ + n, s2);
}

// init_aux: bstk init; zero fold vectors and raw stat buffers. grid 96 x 512.
__global__ void init_aux(const float* __restrict__ bo_sa, const float* __restrict__ bo_ca,
                         float* __restrict__ bstk,
                         float* __restrict__ v1f, float* __restrict__ v2f,
                         float* __restrict__ v1h1, float* __restrict__ v2h1,
                         float* __restrict__ v1h2, float* __restrict__ v2h2,
                         float* __restrict__ rsA, float* __restrict__ rsB,
                         float* __restrict__ rsC)
{
    const int i = blockIdx.x * 512 + threadIdx.x;
    if (i < DMODEL) bstk[i] = bo_sa[i] + bo_ca[i];
    if (i < FDIM) { v1f[i] = 0.f; v2f[i] = 0.f; }
    if (i < NH * HD) { v1h1[i] = 0.f; v2h1[i] = 0.f; }
    if (i < NH * OUTD) { v1h2[i] = 0.f; v2h2[i] = 0.f; }
    if (i < 2 * BATCH) { rsA[i] = 0.f; rsB[i] = 0.f; }
    if (i < 2 * BATCH * NH) rsC[i] = 0.f;
}

__global__ void prep_all(
    const float* w_in, float* wp_in,
    const float* wo_sa, const float* wo_ca, float* wp_o,
    const float* w_ff1, float* wp_ff1, const float* ln3_g, const float* ln3_b,
    const float* w_ff2, float* wp_ff2,
    const float* wh1, float* wp_h1, const float* lnout_g, const float* lnout_b,
    const float* wh2, float* wp_h2, const float* lnh_g, const float* lnh_b,
    const float* bv_sa, const float* bv_ca, float* bstk,
    float* v1f, float* v2f, float* v1h1, float* v2h1, float* v1h2, float* v2h2)
{
    int bid = blockIdx.x;
    if (bid < 2048) { pack_dev(w_in, wp_in, DIN, DMODEL, nullptr, 0, bid & 3, bid >> 2, 0); return; }
    bid -= 2048;
    if (bid < 256) { pack_dev(wo_sa, wp_o, DMODEL, DMODEL, nullptr, 0, bid & 3, bid >> 2, 0); return; }
    bid -= 256;
    if (bid < 256) { pack_dev(wo_ca, wp_o + DMODEL * DMODEL, DMODEL, DMODEL, nullptr, 0, bid & 3, bid >> 2, 0); return; }
    bid -= 256;
    if (bid < 1024) { pack_dev(w_ff1, wp_ff1, DMODEL, FDIM, ln3_g, 0, bid & 15, bid >> 4, 0); return; }
    bid -= 1024;
    if (bid < 1024) { pack_dev(w_ff2, wp_ff2, FDIM, DMODEL, nullptr, 0, bid & 3, bid >> 2, 0); return; }
    bid -= 1024;
    if (bid < 384) { int l = bid & 127, z = bid >> 7;
        pack_dev(wh1, wp_h1, DMODEL, HD, lnout_g, 0, l & 1, l >> 1, z); return; }
    bid -= 384;
    if (bid < 672) { int l = bid % 224, z = bid / 224;
        pack_dev(wh2, wp_h2, HD, OUTD, lnh_g, HD, l % 7, l / 7, z); return; }
    bid -= 672;
    if (bid < 32) {
        const int n  = (bid & 3) * 128 + threadIdx.x;
        const int k0 = (bid >> 2) * 64;
        float a0 = 0.f;
#pragma unroll 8
        for (int k = 0; k < 64; k++)
            a0 += bv_sa[k0 + k] * wo_sa[(long)(k0 + k) * DMODEL + n]
                + bv_ca[k0 + k] * wo_ca[(long)(k0 + k) * DMODEL + n];
        atomicAdd(bstk + n, a0);
        return;
    }
    bid -= 32;
    if (bid < 128) { vfold_dev(w_ff1, ln3_g, ln3_b, v1f, v2f, DMODEL, FDIM, 0, 0, bid & 15, bid >> 4, 0); return; }
    bid -= 128;
    if (bid < 48) { int l = bid & 15, z = bid >> 4;
        vfold_dev(wh1, lnout_g, lnout_b, v1h1, v2h1, DMODEL, HD, 0, HD, l & 1, l >> 1, z); return; }
    bid -= 48;
    { int l = bid % 28, z = bid / 28;
        vfold_dev(wh2, lnh_g, lnh_b, v1h2, v2h2, HD, OUTD, HD, OUTD, l % 7, l / 7, z); }
}

// lncat: cat[row, 0:512] = ln1(h[row])   (h-half read directly by F_SPLITA GEMM)
__global__ void lncat_kernel(const float* __restrict__ in, float* __restrict__ cat,
                             const float* __restrict__ g, const float* __restrict__ b)
{
    __shared__ float red[8];
    const int row = blockIdx.x;
    const float* x = in + (long)row * DMODEL;
    float* y = cat + (long)row * DMODEL;
    const int i = threadIdx.x * 4;

    float4 v = *(const float4*)(x + i);
    float s  = v.x + v.y + v.z + v.w;
    float s2 = v.x * v.x + v.y * v.y + v.z * v.z + v.w * v.w;
#pragma unroll
    for (int o = 16; o; o >>= 1) {
        s  += __shfl_xor_sync(0xffffffffu, s, o);
        s2 += __shfl_xor_sync(0xffffffffu, s2, o);
    }
    const int w = threadIdx.x >> 5;
    if ((threadIdx.x & 31) == 0) { red[w] = s; red[4 + w] = s2; }
    __syncthreads();
    if (threadIdx.x == 0) {
        float ts = 0.f, ts2 = 0.f;
#pragma unroll
        for (int j = 0; j < 4; j++) { ts += red[j]; ts2 += red[4 + j]; }
        red[0] = ts; red[4] = ts2;
    }
    __syncthreads();
    const float mean = red[0] / DMODEL;
    const float var  = red[4] / DMODEL - mean * mean;
    const float inv  = rsqrtf(var + 1e-5f);
    float4 gg = *(const float4*)(g + i);
    float4 bb = *(const float4*)(b + i);
    float4 o;
    o.x = (v.x - mean) * inv * gg.x + bb.x;
    o.y = (v.y - mean) * inv * gg.y + bb.y;
    o.z = (v.z - mean) * inv * gg.z + bb.z;
    o.w = (v.w - mean) * inv * gg.w + bb.w;
    *(float4*)(y + i) = o;
}

// ---------------------------------------------------------------------------
// Launch — 10 launches (R12 order)
// ---------------------------------------------------------------------------
extern "C" void kernel_launch(void* const* d_in, const int* in_sizes, int n_in,
                              void* d_out, int out_size)
{
    const float* x      = (const float*)d_in[0];
    const float* w_in   = (const float*)d_in[1];
    const float* b_in   = (const float*)d_in[2];
    const float* pos    = (const float*)d_in[3];
    const float* ln1_g  = (const float*)d_in[4];
    const float* ln1_b  = (const float*)d_in[5];
    const float* wv_sa  = (const float*)d_in[6];
    const float* bv_sa  = (const float*)d_in[7];
    const float* wo_sa  = (const float*)d_in[8];
    const float* bo_sa  = (const float*)d_in[9];
    const float* wv_ca  = (const float*)d_in[12];
    const float* bv_ca  = (const float*)d_in[13];
    const float* wo_ca  = (const float*)d_in[14];
    const float* bo_ca  = (const float*)d_in[15];
    const float* ln3_g  = (const float*)d_in[16];
    const float* ln3_b  = (const float*)d_in[17];
    const float* w_ff1  = (const float*)d_in[18];
    const float* b_ff1  = (const float*)d_in[19];
    const float* w_ff2  = (const float*)d_in[20];
    const float* b_ff2  = (const float*)d_in[21];
    const float* lnout_g= (const float*)d_in[22];
    const float* lnout_b= (const float*)d_in[23];
    const float* wh1    = (const float*)d_in[24];
    const float* bh1    = (const float*)d_in[25];
    const float* lnh_g  = (const float*)d_in[26];
    const float* lnh_b  = (const float*)d_in[27];
    const float* wh2    = (const float*)d_in[28];
    const float* bh2    = (const float*)d_in[29];
    float* out = (float*)d_out;

    float *h, *cat, *ff, *zz, *bstk;
    float *wp_in, *wp_o, *wp_stk, *wp_ff1, *wp_ff2, *wp_h1, *wp_h2;
    float *v1f, *v2f, *v1h1, *v2h1, *v1h2, *v2h2;
    float2 *rs3, *rsO, *rsH;
    cudaGetSymbolAddress((void**)&h,    g_h);
    cudaGetSymbolAddress((void**)&cat,  g_cat);
    cudaGetSymbolAddress((void**)&ff,   g_ff);
    cudaGetSymbolAddress((void**)&zz,   g_z);
    cudaGetSymbolAddress((void**)&bstk, g_bstk);
    cudaGetSymbolAddress((void**)&wp_in,  g_wp_in);
    cudaGetSymbolAddress((void**)&wp_o,   g_wp_o);
    cudaGetSymbolAddress((void**)&wp_stk, g_wp_stk);
    cudaGetSymbolAddress((void**)&wp_ff1, g_wp_ff1);
    cudaGetSymbolAddress((void**)&wp_ff2, g_wp_ff2);
    cudaGetSymbolAddress((void**)&wp_h1,  g_wp_h1);
    cudaGetSymbolAddress((void**)&wp_h2,  g_wp_h2);
    cudaGetSymbolAddress((void**)&v1f,  g_v1_ff1);
    cudaGetSymbolAddress((void**)&v2f,  g_v2_ff1);
    cudaGetSymbolAddress((void**)&v1h1, g_v1_h1);
    cudaGetSymbolAddress((void**)&v2h1, g_v2_h1);
    cudaGetSymbolAddress((void**)&v1h2, g_v1_h2);
    cudaGetSymbolAddress((void**)&v2h2, g_v2_h2);
    cudaGetSymbolAddress((void**)&rs3, g_rs_ln3);
    cudaGetSymbolAddress((void**)&rsO, g_rs_lout);
    cudaGetSymbolAddress((void**)&rsH, g_rs_lnh);

    cudaFuncSetAttribute(gemm_big<F_B2>,            cudaFuncAttributeMaxDynamicSharedMemorySize, SMB_BIG);
    cudaFuncSetAttribute(gemm_big<F_RES | F_STAT | F_SPLITA>, cudaFuncAttributeMaxDynamicSharedMemorySize, SMB_BIG);
    cudaFuncSetAttribute(gemm_big<F_RES | F_STAT>,  cudaFuncAttributeMaxDynamicSharedMemorySize, SMB_BIG);
    cudaFuncSetAttribute(gemm_big<F_LNA | F_GELU>,  cudaFuncAttributeMaxDynamicSharedMemorySize, SMB_BIG);
    cudaFuncSetAttribute(gemm_big<F_LNA | F_GELU | F_STAT>, cudaFuncAttributeMaxDynamicSharedMemorySize, SMB_BIG);
    cudaFuncSetAttribute(gemm_sm<F_LNA>,            cudaFuncAttributeMaxDynamicSharedMemorySize, SMB_SM);
    cudaFuncSetAttribute(foldgemm,                  cudaFuncAttributeMaxDynamicSharedMemorySize, SMB_SM);

    const int MG = BATCH / BM;  // 64
    const float invD = 1.f / DMODEL, invH = 1.f / HD;

    // [0] init (zeroes stat buffers — required every replay)
    init_aux<<<96, 512>>>(bo_sa, bo_ca, bstk, v1f, v2f, v1h1, v2h1, v1h2, v2h2,
                          (float*)rs3, (float*)rsO, (float*)rsH);
    // [1] all packs + folds
    prep_all<<<5956, 128>>>(
        w_in, wp_in, wo_sa, wo_ca, wp_o,
        w_ff1, wp_ff1, ln3_g, ln3_b, w_ff2, wp_ff2,
        wh1, wp_h1, lnout_g, lnout_b, wh2, wp_h2, lnh_g, lnh_b,
        bv_sa, bv_ca, bstk, v1f, v2f, v1h1, v2h1, v1h2, v2h2);
    // [2] attention folds -> packed stacked weight
    foldgemm<<<dim3(DMODEL / SBN, DMODEL / BM, 2), THREADS, SMB_SM>>>(wv_sa, wv_ca, wp_o, wp_stk);
    // [3] gemm1: h = x @ w_in + b_in + pos
    gemm_big<F_B2><<<dim3(DMODEL / BN, MG, 1), THREADS, SMB_BIG>>>(
        x, DIN, 0, wp_in, DMODEL, 0, h, DMODEL, 0, DIN, b_in, 0, pos, nullptr,
        nullptr, 0, 0.f, nullptr, nullptr, 0, nullptr, 0, 0, nullptr);
    // [4] cat = ln1(h)   (LN half only; h read directly via F_SPLITA)
    lncat_kernel<<<BATCH, 128>>>(h, cat, ln1_g, ln1_b);
    // [5] h = h + [cat|h] @ Wstk + bstk ; accumulate ln3 stats  (split A)
    gemm_big<F_RES | F_STAT | F_SPLITA><<<dim3(DMODEL / BN, MG, 1), THREADS, SMB_BIG>>>(
        cat, DMODEL, 0, wp_stk, DMODEL, 0, h, DMODEL, 0, 2 * DMODEL,
        bstk, 0, nullptr, h, nullptr, 0, 0.f, nullptr, nullptr, 0, rs3, 1, 0, h);
    // [6] ff = gelu(ln3(h) @ w_ff1 + b_ff1)   [LN from raw stats]
    gemm_big<F_LNA | F_GELU><<<dim3(FDIM / BN, MG, 1), THREADS, SMB_BIG>>>(
        h, DMODEL, 0, wp_ff1, FDIM, 0, ff, FDIM, 0, DMODEL, b_ff1, 0, nullptr, nullptr,
        rs3, 1, invD, v1f, v2f, 0, nullptr, 0, 0, nullptr);
    // [7] h = h + ff @ w_ff2 + b_ff2 ; accumulate lnout stats
    gemm_big<F_RES | F_STAT><<<dim3(DMODEL / BN, MG, 1), THREADS, SMB_BIG>>>(
        ff, FDIM, 0, wp_ff2, DMODEL, 0, h, DMODEL, 0, FDIM, b_ff2, 0, nullptr, h,
        nullptr, 0, 0.f, nullptr, nullptr, 0, rsO, 1, 0, nullptr);
    // [8] zz = gelu(lnout(h) @ wh1 + bh1) ; accumulate lnh stats
    gemm_big<F_LNA | F_GELU | F_STAT><<<dim3(HD / BN, MG, NH), THREADS, SMB_BIG>>>(
        h, DMODEL, 0, wp_h1, HD, (long)DMODEL * HD, zz, NH * HD, HD,
        DMODEL, bh1, HD, nullptr, nullptr, rsO, 1, invD, v1h1, v2h1, HD,
        rsH, NH, 1, nullptr);
    // [9] out = ln_head(zz) @ wh2 + bh2
    gemm_sm<F_LNA><<<dim3(OUTD / SBN, MG, NH), THREADS, SMB_SM>>>(
        zz, NH * HD, HD, wp_h2, OUTD, (long)HD * OUTD, out, NH * OUTD, OUTD,
        HD, bh2, OUTD, rsH, NH, 1, invH, v1h2, v2h2, OUTD);
}